// round 2
// baseline (speedup 1.0000x reference)
#include <cuda_runtime.h>
#include <stdint.h>

#define N     8192
#define DIM   64
#define BIGF  1e30f

// Scratch (allocation-free rule: __device__ globals)
__device__ float g_D[(size_t)N * (size_t)N];   // 256 MB distance matrix
__device__ float g_sq[N];                       // squared norms

// ---------------------------------------------------------------------------
// Kernel 1: squared norms
// ---------------------------------------------------------------------------
__global__ void norms_kernel(const float* __restrict__ x) {
    int i = blockIdx.x * blockDim.x + threadIdx.x;
    if (i < N) {
        const float4* p = (const float4*)(x + (size_t)i * DIM);
        float s = 0.0f;
        #pragma unroll
        for (int k = 0; k < DIM / 4; k++) {
            float4 v = p[k];
            s += v.x * v.x + v.y * v.y + v.z * v.z + v.w * v.w;
        }
        g_sq[i] = s;
    }
}

// ---------------------------------------------------------------------------
// Kernel 2: D[i][j] = sqrt(max(sq_i + sq_j - 2*x_i.x_j, 0))
// 64x64 output tile per block, 16x16 threads, 4x4 per thread, K=64 fully staged.
// ---------------------------------------------------------------------------
__global__ void dist_kernel(const float* __restrict__ x) {
    __shared__ float As[64][65];
    __shared__ float Bs[64][65];

    const int tx = threadIdx.x, ty = threadIdx.y;
    const int tid = ty * 16 + tx;
    const int bi = blockIdx.y, bj = blockIdx.x;

    #pragma unroll
    for (int i = 0; i < 4; i++) {
        int idx = tid + 256 * i;
        int r   = idx >> 4;
        int c4  = idx & 15;
        float4 a = ((const float4*)(x + (size_t)(bi * 64 + r) * DIM))[c4];
        As[r][c4 * 4 + 0] = a.x; As[r][c4 * 4 + 1] = a.y;
        As[r][c4 * 4 + 2] = a.z; As[r][c4 * 4 + 3] = a.w;
        float4 b = ((const float4*)(x + (size_t)(bj * 64 + r) * DIM))[c4];
        Bs[r][c4 * 4 + 0] = b.x; Bs[r][c4 * 4 + 1] = b.y;
        Bs[r][c4 * 4 + 2] = b.z; Bs[r][c4 * 4 + 3] = b.w;
    }
    __syncthreads();

    float acc[4][4];
    #pragma unroll
    for (int i = 0; i < 4; i++)
        #pragma unroll
        for (int j = 0; j < 4; j++) acc[i][j] = 0.0f;

    #pragma unroll
    for (int k = 0; k < 64; k++) {
        float a[4], b[4];
        #pragma unroll
        for (int i = 0; i < 4; i++) a[i] = As[ty * 4 + i][k];
        #pragma unroll
        for (int j = 0; j < 4; j++) b[j] = Bs[tx * 4 + j][k];
        #pragma unroll
        for (int i = 0; i < 4; i++)
            #pragma unroll
            for (int j = 0; j < 4; j++)
                acc[i][j] = fmaf(a[i], b[j], acc[i][j]);
    }

    const int row0 = bi * 64 + ty * 4;
    const int col0 = bj * 64 + tx * 4;
    float sqc0 = g_sq[col0 + 0], sqc1 = g_sq[col0 + 1];
    float sqc2 = g_sq[col0 + 2], sqc3 = g_sq[col0 + 3];
    #pragma unroll
    for (int i = 0; i < 4; i++) {
        float sqr = g_sq[row0 + i];
        float4 o;
        o.x = sqrtf(fmaxf(sqr + sqc0 - 2.0f * acc[i][0], 0.0f));
        o.y = sqrtf(fmaxf(sqr + sqc1 - 2.0f * acc[i][1], 0.0f));
        o.z = sqrtf(fmaxf(sqr + sqc2 - 2.0f * acc[i][2], 0.0f));
        o.w = sqrtf(fmaxf(sqr + sqc3 - 2.0f * acc[i][3], 0.0f));
        *(float4*)(g_D + (size_t)(row0 + i) * N + col0) = o;
    }
}

// ---------------------------------------------------------------------------
// Kernel 3: Prim's MST, pipelined. 1024 threads, 8 CONTIGUOUS verts/thread.
// While row j is in flight (2x LDG.128/thread), the block reduces the OLD
// mind array; when the row lands only the row-side reduce is on the chain.
//   pack(min(a,b),i) = min(pack(a,i),pack(b,i))  ->  argmin(updated mind)
//   = min(reduce(mind), reduce(row)), exact first-index tie-break preserved.
// ---------------------------------------------------------------------------
__device__ __forceinline__ unsigned redux_min_u32(unsigned v) {
    unsigned r;
    asm volatile("redux.sync.min.u32 %0, %1, 0xffffffff;" : "=r"(r) : "r"(v));
    return r;
}

// Two-phase warp min of packed (valbits<<13 | idx13): exact value + first index
__device__ __forceinline__ unsigned long long warp_min_pack(unsigned long long p) {
    unsigned vb = (unsigned)(p >> 13);
    unsigned id = (unsigned)p & 0x1FFFu;
    unsigned wv = redux_min_u32(vb);
    unsigned wi = redux_min_u32((vb == wv) ? id : 0xFFFFFFFFu);
    return ((unsigned long long)wv << 13) | (unsigned long long)wi;
}

__global__ void __launch_bounds__(1024, 1) prim_kernel(float* __restrict__ out) {
    const int t    = threadIdx.x;
    const int lane = t & 31;
    const int warp = t >> 5;
    const int vbase = t << 3;            // this thread owns vertices [8t, 8t+8)

    float mind[8];
    #pragma unroll
    for (int s = 0; s < 8; s++) mind[s] = BIGF;
    unsigned intree = (t == 0) ? 1u : 0u;   // vertex 0 (thread 0, slot 0) in tree

    __shared__ unsigned long long parts_old[32];
    __shared__ unsigned long long parts_row[32];

    unsigned j = 0;

    for (int step = 0; step < N - 1; ++step) {
        // ---- issue the row load first (2x LDG.128, streaming) ----
        const float4* rp = (const float4*)(g_D + (size_t)j * N + vbase);
        float4 q0 = __ldcs(rp);
        float4 q1 = __ldcs(rp + 1);

        // ---- shadowed phase: block-reduce OLD mind over non-tree ----
        unsigned long long bo = ~0ull;
        #pragma unroll
        for (int s = 0; s < 8; s++) {
            if (!((intree >> s) & 1u)) {
                unsigned long long p =
                    ((unsigned long long)__float_as_uint(mind[s]) << 13) |
                    (unsigned)(vbase + s);
                bo = (p < bo) ? p : bo;
            }
        }
        bo = warp_min_pack(bo);
        if (lane == 0) parts_old[warp] = bo;
        __syncthreads();
        unsigned long long R_old = warp_min_pack(parts_old[lane]);

        // ---- row lands: row-side reduce over non-tree ----
        float r[8];
        r[0] = q0.x; r[1] = q0.y; r[2] = q0.z; r[3] = q0.w;
        r[4] = q1.x; r[5] = q1.y; r[6] = q1.z; r[7] = q1.w;

        unsigned long long br = ~0ull;
        #pragma unroll
        for (int s = 0; s < 8; s++) {
            if (!((intree >> s) & 1u)) {
                unsigned long long p =
                    ((unsigned long long)__float_as_uint(r[s]) << 13) |
                    (unsigned)(vbase + s);
                br = (p < br) ? p : br;
            }
        }
        br = warp_min_pack(br);
        if (lane == 0) parts_row[warp] = br;
        __syncthreads();
        unsigned long long R_row = warp_min_pack(parts_row[lane]);

        // ---- combine, emit, bookkeeping ----
        unsigned long long fin = (R_old < R_row) ? R_old : R_row;
        j = (unsigned)fin & 0x1FFFu;
        if (t == 0) {
            out[2 * step]     = 0.0f;
            out[2 * step + 1] = __uint_as_float((unsigned)(fin >> 13));
        }
        if ((j >> 3) == (unsigned)t) intree |= 1u << (j & 7u);

        // mind update (feeds next step's shadowed reduce; off critical path)
        #pragma unroll
        for (int s = 0; s < 8; s++) mind[s] = fminf(mind[s], r[s]);
    }
}

// ---------------------------------------------------------------------------
extern "C" void kernel_launch(void* const* d_in, const int* in_sizes, int n_in,
                              void* d_out, int out_size) {
    const float* x = (const float*)d_in[0];
    float* out = (float*)d_out;

    norms_kernel<<<(N + 255) / 256, 256>>>(x);

    dim3 gblk(16, 16);
    dim3 ggrid(N / 64, N / 64);
    dist_kernel<<<ggrid, gblk>>>(x);

    prim_kernel<<<1, 1024>>>(out);
}

// round 4
// speedup vs baseline: 2.1813x; 2.1813x over previous
#include <cuda_runtime.h>
#include <stdint.h>

#define N        8192
#define DIM      64
#define NROUNDS  13
#define NTHREADS 1024

// ---------------- scratch (__device__ globals; no allocations) -------------
__device__ float              g_D[(size_t)N * (size_t)N];  // 256 MB fp32
__device__ float              g_sq[N];
__device__ unsigned long long g_best[N];       // per-vertex best: (dbits<<13)|u
__device__ unsigned long long g_compbest[N];   // per-comp best:  (dbits<<26)|(v<<13)|u
__device__ unsigned short     g_comp[N];       // component label (a root id)
__device__ int                g_parent[N];
__device__ unsigned long long g_edges[N];      // MST edges, packed like compbest
__device__ int                g_edge_cnt;
__device__ int                g_done;

__device__ __forceinline__ unsigned redux_min_u32(unsigned v) {
    unsigned r;
    asm volatile("redux.sync.min.u32 %0, %1, 0xffffffff;" : "=r"(r) : "r"(v));
    return r;
}

// ---------------------------------------------------------------------------
__global__ void init_kernel() {
    int v = blockIdx.x * blockDim.x + threadIdx.x;
    if (v < N) {
        g_comp[v]  = (unsigned short)v;
        g_best[v]  = ~0ull;
    }
    if (v == 0) { g_edge_cnt = 0; g_done = 0; }
}

// ---------------------------------------------------------------------------
__global__ void norms_kernel(const float* __restrict__ x) {
    int i = blockIdx.x * blockDim.x + threadIdx.x;
    if (i < N) {
        const float4* p = (const float4*)(x + (size_t)i * DIM);
        float s = 0.0f;
        #pragma unroll
        for (int k = 0; k < DIM / 4; k++) {
            float4 v = p[k];
            s += v.x * v.x + v.y * v.y + v.z * v.z + v.w * v.w;
        }
        g_sq[i] = s;
    }
}

// ---------------------------------------------------------------------------
// D[i][j] = sqrt(max(sq_i + sq_j - 2*x_i.x_j, 0)), 64x64 tile per block.
// ---------------------------------------------------------------------------
__global__ void dist_kernel(const float* __restrict__ x) {
    __shared__ float As[64][65];
    __shared__ float Bs[64][65];

    const int tx = threadIdx.x, ty = threadIdx.y;
    const int tid = ty * 16 + tx;
    const int bi = blockIdx.y, bj = blockIdx.x;

    #pragma unroll
    for (int i = 0; i < 4; i++) {
        int idx = tid + 256 * i;
        int r   = idx >> 4;
        int c4  = idx & 15;
        float4 a = ((const float4*)(x + (size_t)(bi * 64 + r) * DIM))[c4];
        As[r][c4 * 4 + 0] = a.x; As[r][c4 * 4 + 1] = a.y;
        As[r][c4 * 4 + 2] = a.z; As[r][c4 * 4 + 3] = a.w;
        float4 b = ((const float4*)(x + (size_t)(bj * 64 + r) * DIM))[c4];
        Bs[r][c4 * 4 + 0] = b.x; Bs[r][c4 * 4 + 1] = b.y;
        Bs[r][c4 * 4 + 2] = b.z; Bs[r][c4 * 4 + 3] = b.w;
    }
    __syncthreads();

    float acc[4][4];
    #pragma unroll
    for (int i = 0; i < 4; i++)
        #pragma unroll
        for (int j = 0; j < 4; j++) acc[i][j] = 0.0f;

    #pragma unroll
    for (int k = 0; k < 64; k++) {
        float a[4], b[4];
        #pragma unroll
        for (int i = 0; i < 4; i++) a[i] = As[ty * 4 + i][k];
        #pragma unroll
        for (int j = 0; j < 4; j++) b[j] = Bs[tx * 4 + j][k];
        #pragma unroll
        for (int i = 0; i < 4; i++)
            #pragma unroll
            for (int j = 0; j < 4; j++)
                acc[i][j] = fmaf(a[i], b[j], acc[i][j]);
    }

    const int row0 = bi * 64 + ty * 4;
    const int col0 = bj * 64 + tx * 4;
    float sqc0 = g_sq[col0 + 0], sqc1 = g_sq[col0 + 1];
    float sqc2 = g_sq[col0 + 2], sqc3 = g_sq[col0 + 3];
    #pragma unroll
    for (int i = 0; i < 4; i++) {
        float sqr = g_sq[row0 + i];
        float4 o;
        o.x = sqrtf(fmaxf(sqr + sqc0 - 2.0f * acc[i][0], 0.0f));
        o.y = sqrtf(fmaxf(sqr + sqc1 - 2.0f * acc[i][1], 0.0f));
        o.z = sqrtf(fmaxf(sqr + sqc2 - 2.0f * acc[i][2], 0.0f));
        o.w = sqrtf(fmaxf(sqr + sqc3 - 2.0f * acc[i][3], 0.0f));
        *(float4*)(g_D + (size_t)(row0 + i) * N + col0) = o;
    }
}

// ---------------------------------------------------------------------------
// Boruvka scan: per-vertex min outgoing edge (masked row min). One block/row.
// Cached g_best[v] stays valid while its endpoint remains outside comp(v):
// candidate set only shrinks as comps merge, so the old min is still the min.
// ---------------------------------------------------------------------------
__global__ void scan_kernel(int round) {
    if (g_done) return;
    const int v = blockIdx.x;
    const int t = threadIdx.x;                 // 256 threads
    const unsigned short myc = g_comp[v];

    __shared__ int do_scan;
    if (t == 0) {
        int ds = 1;
        if (round > 0) {
            unsigned u = (unsigned)g_best[v] & 0x1FFFu;
            if (g_comp[u] != myc) ds = 0;      // cache still valid
        }
        do_scan = ds;
    }
    __syncthreads();
    if (!do_scan) return;

    const float* row = g_D + (size_t)v * N;
    unsigned lv = 0xFFFFFFFFu, li = 0;
    #pragma unroll
    for (int c = 0; c < 8; c++) {
        int u0 = c * 1024 + t * 4;
        float4  d4 = *(const float4*)(row + u0);
        ushort4 c4 = *(const ushort4*)(g_comp + u0);
        if (c4.x != myc) { unsigned db = __float_as_uint(d4.x); if (db < lv) { lv = db; li = u0;     } }
        if (c4.y != myc) { unsigned db = __float_as_uint(d4.y); if (db < lv) { lv = db; li = u0 + 1; } }
        if (c4.z != myc) { unsigned db = __float_as_uint(d4.z); if (db < lv) { lv = db; li = u0 + 2; } }
        if (c4.w != myc) { unsigned db = __float_as_uint(d4.w); if (db < lv) { lv = db; li = u0 + 3; } }
    }

    __shared__ unsigned long long parts[8];
    unsigned wv = redux_min_u32(lv);
    unsigned wi = redux_min_u32((lv == wv) ? li : 0xFFFFFFFFu);
    if ((t & 31) == 0) parts[t >> 5] = ((unsigned long long)wv << 13) | wi;
    __syncthreads();
    if (t < 32) {
        unsigned long long p = (t < 8) ? parts[t] : ~0ull;
        unsigned v2 = (unsigned)(p >> 13), i2 = (unsigned)p & 0x1FFFu;
        unsigned gv = redux_min_u32(v2);
        unsigned gi = redux_min_u32((v2 == gv) ? i2 : 0xFFFFFFFFu);
        if (t == 0) g_best[v] = ((unsigned long long)gv << 13) | gi;
    }
}

// ---------------------------------------------------------------------------
// Boruvka pick+union: per-comp min edge, hook, 2-cycle fix, pointer jump,
// relabel. Single block.
// ---------------------------------------------------------------------------
__global__ void __launch_bounds__(NTHREADS, 1) pick_kernel() {
    if (g_done) return;
    const int t = threadIdx.x;

    for (int v = t; v < N; v += NTHREADS) { g_compbest[v] = ~0ull; g_parent[v] = v; }
    __syncthreads();

    for (int v = t; v < N; v += NTHREADS) {
        unsigned long long b = g_best[v];
        unsigned long long w = b >> 13;                 // 31-bit fp32 dist bits
        unsigned u = (unsigned)b & 0x1FFFu;
        unsigned c = g_comp[v];
        atomicMin(&g_compbest[c], (w << 26) | ((unsigned long long)v << 13) | u);
    }
    __syncthreads();

    // hooks + edge emission (distinct weights => mutual pair is the SAME edge)
    for (int v = t; v < N; v += NTHREADS) {
        if ((int)g_comp[v] == v) {
            unsigned long long cb = g_compbest[v];
            if (cb != ~0ull) {
                unsigned b = (unsigned)cb & 0x1FFFu;             // outside endpoint
                unsigned a = (unsigned)(cb >> 13) & 0x1FFFu;     // inside endpoint
                unsigned d = g_comp[b];
                g_parent[v] = (int)d;
                unsigned long long cbd = g_compbest[d];
                unsigned b2 = (unsigned)cbd & 0x1FFFu;
                unsigned a2 = (unsigned)(cbd >> 13) & 0x1FFFu;
                bool mutual = (a2 == b && b2 == a);
                if (!mutual || v < (int)d) {
                    int pos = atomicAdd(&g_edge_cnt, 1);
                    g_edges[pos] = cb;
                }
            }
        }
    }
    __syncthreads();

    // break 2-cycles: smaller id becomes root
    for (int v = t; v < N; v += NTHREADS) {
        int p = g_parent[v];
        if (g_parent[p] == v && v < p) g_parent[v] = v;
    }
    __syncthreads();

    // pointer jumping (races benign: always jumps toward an ancestor)
    for (int it = 0; it < 13; it++) {
        for (int v = t; v < N; v += NTHREADS) g_parent[v] = g_parent[g_parent[v]];
        __syncthreads();
    }

    // relabel
    unsigned short nc[N / NTHREADS];
    #pragma unroll
    for (int k = 0; k < N / NTHREADS; k++)
        nc[k] = (unsigned short)g_parent[g_comp[t + k * NTHREADS]];
    __syncthreads();
    #pragma unroll
    for (int k = 0; k < N / NTHREADS; k++)
        g_comp[t + k * NTHREADS] = nc[k];
    __syncthreads();

    if (t == 0 && g_edge_cnt >= N - 1) g_done = 1;
}

// ---------------------------------------------------------------------------
// Replay: Prim on the MST (8191 edges) — exact order/values, no gmem loads
// in the step loop. CSR + adjacency live in dynamic shared memory.
// ---------------------------------------------------------------------------
#define SM_ROWPTR_U32  0            // 8200 u32
#define SM_CURSOR_U32  8200         // 8200 u32
#define SM_ADJ_OFF     (16400 * 4)  // byte offset; 16384 u64
#define SM_PARTS_OFF   (SM_ADJ_OFF + 16384 * 8)    // 64 u64 (double buffer)
#define SM_TOTAL       (SM_PARTS_OFF + 64 * 8 + 256)

__global__ void __launch_bounds__(NTHREADS, 1) replay_kernel(float* __restrict__ out) {
    extern __shared__ unsigned char smraw[];
    unsigned*           rowptr = (unsigned*)smraw;
    unsigned*           cursor = rowptr + SM_CURSOR_U32;
    unsigned long long* adj    = (unsigned long long*)(smraw + SM_ADJ_OFF);
    unsigned long long* parts  = (unsigned long long*)(smraw + SM_PARTS_OFF);
    unsigned*           wsum   = (unsigned*)(parts + 64);   // 32 u32 scan scratch

    const int t = threadIdx.x, lane = t & 31, warp = t >> 5;
    const int ne = N - 1;

    // ---- build CSR ----
    for (int v = t; v < N; v += NTHREADS) cursor[v] = 0;
    __syncthreads();
    for (int e = t; e < ne; e += NTHREADS) {
        unsigned long long ed = g_edges[e];
        unsigned a = (unsigned)(ed >> 13) & 0x1FFFu;
        unsigned b = (unsigned)ed & 0x1FFFu;
        atomicAdd(&cursor[a], 1u);
        atomicAdd(&cursor[b], 1u);
    }
    __syncthreads();

    // exclusive scan of degrees (thread owns 8 consecutive)
    unsigned loc[8], s = 0;
    #pragma unroll
    for (int k = 0; k < 8; k++) { loc[k] = s; s += cursor[t * 8 + k]; }
    unsigned x = s;
    #pragma unroll
    for (int o = 1; o < 32; o <<= 1) {
        unsigned y = __shfl_up_sync(0xffffffffu, x, o);
        if (lane >= o) x += y;
    }
    if (lane == 31) wsum[warp] = x;
    __syncthreads();
    unsigned wt = wsum[lane];
    unsigned xx = wt;
    #pragma unroll
    for (int o = 1; o < 32; o <<= 1) {
        unsigned y = __shfl_up_sync(0xffffffffu, xx, o);
        if (lane >= o) xx += y;
    }
    unsigned wbase = __shfl_sync(0xffffffffu, xx, warp) - wsum[warp];
    unsigned base = wbase + (x - s);
    __syncthreads();
    #pragma unroll
    for (int k = 0; k < 8; k++) rowptr[t * 8 + k] = base + loc[k];
    if (t == NTHREADS - 1) rowptr[N] = base + s;
    __syncthreads();
    for (int v = t; v < N; v += NTHREADS) cursor[v] = rowptr[v];
    __syncthreads();
    for (int e = t; e < ne; e += NTHREADS) {
        unsigned long long ed = g_edges[e];
        unsigned long long w = ed >> 26;
        unsigned a = (unsigned)(ed >> 13) & 0x1FFFu;
        unsigned b = (unsigned)ed & 0x1FFFu;
        unsigned pa = atomicAdd(&cursor[a], 1u);
        adj[pa] = (w << 13) | b;
        unsigned pb = atomicAdd(&cursor[b], 1u);
        adj[pb] = (w << 13) | a;
    }
    __syncthreads();

    // ---- step loop ----
    unsigned key[8];                       // fp32 bits; 0x7F800000 unreached, 0xFFFFFFFF dead
    #pragma unroll
    for (int k = 0; k < 8; k++) key[k] = 0x7F800000u;
    unsigned intree = (t == 0) ? 1u : 0u;
    if (t == 0) key[0] = 0xFFFFFFFFu;
    const unsigned vb = (unsigned)t << 3;
    unsigned j = 0;

    for (int step = 0; step < N - 1; ++step) {
        // apply adjacency of newly added j (broadcast LDS; all threads same addr)
        unsigned r0 = rowptr[j], r1 = rowptr[j + 1];
        for (unsigned e = r0; e < r1; ++e) {
            unsigned long long a = adj[e];
            unsigned u = (unsigned)a & 0x1FFFu;
            if ((u >> 3) == (unsigned)t) {
                unsigned sl = u & 7u;
                if (!((intree >> sl) & 1u))
                    key[sl] = min(key[sl], (unsigned)(a >> 13));
            }
        }

        unsigned lv = 0xFFFFFFFFu, li = 0;
        #pragma unroll
        for (int k = 0; k < 8; k++)
            if (key[k] < lv) { lv = key[k]; li = vb + k; }

        unsigned wv = redux_min_u32(lv);
        unsigned wi = redux_min_u32((lv == wv) ? li : 0xFFFFFFFFu);
        if (lane == 0) parts[(step & 1) * 32 + warp] =
            ((unsigned long long)wv << 13) | wi;
        __syncthreads();
        unsigned long long p = parts[(step & 1) * 32 + lane];
        unsigned v2 = (unsigned)(p >> 13), i2 = (unsigned)p & 0x1FFFu;
        unsigned gv = redux_min_u32(v2);
        unsigned gi = redux_min_u32((v2 == gv) ? i2 : 0xFFFFFFFFu);

        j = gi;
        if (t == 0) {
            out[2 * step]     = 0.0f;
            out[2 * step + 1] = __uint_as_float(gv);
        }
        if ((j >> 3) == (unsigned)t) {
            intree |= 1u << (j & 7u);
            key[j & 7u] = 0xFFFFFFFFu;
        }
    }
}

// ---------------------------------------------------------------------------
extern "C" void kernel_launch(void* const* d_in, const int* in_sizes, int n_in,
                              void* d_out, int out_size) {
    const float* x = (const float*)d_in[0];
    float* out = (float*)d_out;

    static int attr_set = 0;
    if (!attr_set) {
        cudaFuncSetAttribute(replay_kernel,
                             cudaFuncAttributeMaxDynamicSharedMemorySize, SM_TOTAL);
        attr_set = 1;
    }

    init_kernel<<<(N + 255) / 256, 256>>>();
    norms_kernel<<<(N + 255) / 256, 256>>>(x);

    dim3 gblk(16, 16);
    dim3 ggrid(N / 64, N / 64);
    dist_kernel<<<ggrid, gblk>>>(x);

    for (int r = 0; r < NROUNDS; r++) {
        scan_kernel<<<N, 256>>>(r);
        pick_kernel<<<1, NTHREADS>>>();
    }

    replay_kernel<<<1, NTHREADS, SM_TOTAL>>>(out);
}